// round 3
// baseline (speedup 1.0000x reference)
#include <cuda_runtime.h>
#include <cuda_bf16.h>
#include <math.h>

#define N_Q   4098
#define N_KV  4099
#define CDIM  384
#define HEADS 6
#define HDIM  64

// ---------------- scratch (device globals; allocation-free) ----------------
__device__ __align__(16) float g_pp[64 * CDIM];     // pooling partials
__device__ float  g_cntp[64];                       // count partials
__device__ __align__(16) float g_back[CDIM];        // back token
__device__ int    g_idx[N_KV];                      // kept key -> source row
__device__ int    g_M;                              // number of kept keys
__device__ __align__(16) float g_q[N_Q * CDIM];
__device__ __align__(16) float g_k[N_KV * CDIM];
__device__ __align__(16) float g_v[N_KV * CDIM];
__device__ __align__(16) float g_o[N_Q * CDIM];

// ---------------- 1) background pooling (deterministic, 2-stage) -----------
__global__ void pool_kernel(const float* __restrict__ x, const float* __restrict__ mask)
{
    const int c  = threadIdx.x;            // 384 threads
    const int n0 = blockIdx.x * 64;        // 64 blocks x 64 interior rows = 4096
    float s = 0.f;
    for (int i = 0; i < 64; i++) {
        const int n = n0 + i;
        const float rev = (mask[n] < 0.5f) ? 1.f : 0.f;
        s += rev * x[(1 + n) * CDIM + c];
    }
    g_pp[blockIdx.x * CDIM + c] = s;
    if (c == 0) {
        float cc = 0.f;
        for (int i = 0; i < 64; i++) cc += (mask[n0 + i] < 0.5f) ? 1.f : 0.f;
        g_cntp[blockIdx.x] = cc;
    }
}

__global__ void back_finalize_kernel()
{
    const int c = threadIdx.x;             // 384 threads
    float cnt = 0.f;
    for (int b = 0; b < 64; b++) cnt += g_cntp[b];   // redundant but broadcast-cheap
    float s = 0.f;
    for (int b = 0; b < 64; b++) s += g_pp[b * CDIM + c];
    g_back[c] = s / (cnt + 1e-10f);
}

// ---------------- 2) kept-key compaction (1-block prefix scan) -------------
__global__ void scan_kernel(const float* __restrict__ mask,
                            const float* __restrict__ mask_block)
{
    __shared__ int sc[1024];
    const int t = threadIdx.x;
    const int base = t * 5;                // 1024*5 >= 4099
    int flags[5];
    int cnt = 0;
#pragma unroll
    for (int e = 0; e < 5; e++) {
        int r = base + e;
        int f = 0;
        if (r < N_KV) {
            float mv = (r >= 1 && r <= N_Q - 2) ? mask[r - 1] : mask_block[r];
            f = (mv >= 0.5f) ? 1 : 0;
        }
        flags[e] = f;
        cnt += f;
    }
    sc[t] = cnt;
    __syncthreads();
    for (int off = 1; off < 1024; off <<= 1) {
        int v = (t >= off) ? sc[t - off] : 0;
        __syncthreads();
        sc[t] += v;
        __syncthreads();
    }
    int o = sc[t] - cnt;                   // exclusive prefix
#pragma unroll
    for (int e = 0; e < 5; e++)
        if (flags[e]) g_idx[o++] = base + e;
    if (t == 1023) g_M = sc[1023];
}

// ---------------- 3) projection GEMM: out[m, j] = sum_c A(m,c) * W[j,c] ----
// mode 0: q  = (x + pos[:N]) @ Wq^T           -> g_q   (rows = N_Q)
// mode 1: k  = (kv_x[idx] + pos[idx]) @ Wk^T  -> g_k   (rows = g_M, gathered)
// mode 2: v  = kv_x[idx] @ Wv^T               -> g_v   (rows = g_M, gathered)
// mode 3: o  = g_o @ Wp^T + bp                -> d_out (rows = N_Q)
__global__ __launch_bounds__(256)
void proj_kernel(int mode,
                 const float* __restrict__ x, const float* __restrict__ pos,
                 const float* __restrict__ W, const float* __restrict__ bias,
                 float* __restrict__ out_param)
{
    __shared__ float As[16][68];
    __shared__ float Ws[16][68];

    const int rows = (mode == 1 || mode == 2) ? g_M : N_Q;
    const int m0 = blockIdx.x * 64;
    if (m0 >= rows) return;
    const int j0 = blockIdx.y * 64;

    float* outp = (mode == 0) ? g_q : (mode == 1) ? g_k : (mode == 2) ? g_v : out_param;

    const int tid = threadIdx.x;
    const int tx = tid & 15, ty = tid >> 4;
    const int lr = tid >> 2;              // 0..63 (tile row for loads)
    const int lk = (tid & 3) * 4;         // 0,4,8,12 (k offset for loads)

    float acc[4][4] = {};

    for (int kt = 0; kt < CDIM; kt += 16) {
        // ---- load A fragment (float4 along k) ----
        const int mg = m0 + lr;
        float4 av = make_float4(0.f, 0.f, 0.f, 0.f);
        if (mg < rows) {
            const int c = kt + lk;
            if (mode == 0) {
                float4 xv = *(const float4*)&x[mg * CDIM + c];
                float4 pv = *(const float4*)&pos[mg * CDIM + c];
                av = make_float4(xv.x + pv.x, xv.y + pv.y, xv.z + pv.z, xv.w + pv.w);
            } else if (mode == 3) {
                av = *(const float4*)&g_o[mg * CDIM + c];
            } else {
                const int src = g_idx[mg];
                float4 bv = (src < N_Q) ? *(const float4*)&x[src * CDIM + c]
                                        : *(const float4*)&g_back[c];
                if (mode == 1) {
                    float4 pv = *(const float4*)&pos[src * CDIM + c];
                    av = make_float4(bv.x + pv.x, bv.y + pv.y, bv.z + pv.z, bv.w + pv.w);
                } else {
                    av = bv;
                }
            }
        }
        As[lk + 0][lr] = av.x; As[lk + 1][lr] = av.y;
        As[lk + 2][lr] = av.z; As[lk + 3][lr] = av.w;

        // ---- load W fragment (row j0+lr always < 384) ----
        float4 wv = *(const float4*)&W[(j0 + lr) * CDIM + kt + lk];
        Ws[lk + 0][lr] = wv.x; Ws[lk + 1][lr] = wv.y;
        Ws[lk + 2][lr] = wv.z; Ws[lk + 3][lr] = wv.w;

        __syncthreads();

#pragma unroll
        for (int kk = 0; kk < 16; kk++) {
            float4 a = *(float4*)&As[kk][ty * 4];
            float4 b = *(float4*)&Ws[kk][tx * 4];
            acc[0][0] += a.x * b.x; acc[0][1] += a.x * b.y; acc[0][2] += a.x * b.z; acc[0][3] += a.x * b.w;
            acc[1][0] += a.y * b.x; acc[1][1] += a.y * b.y; acc[1][2] += a.y * b.z; acc[1][3] += a.y * b.w;
            acc[2][0] += a.z * b.x; acc[2][1] += a.z * b.y; acc[2][2] += a.z * b.z; acc[2][3] += a.z * b.w;
            acc[3][0] += a.w * b.x; acc[3][1] += a.w * b.y; acc[3][2] += a.w * b.z; acc[3][3] += a.w * b.w;
        }
        __syncthreads();
    }

#pragma unroll
    for (int r = 0; r < 4; r++) {
        const int mg = m0 + ty * 4 + r;
        if (mg < rows) {
#pragma unroll
            for (int j = 0; j < 4; j++) {
                const int col = j0 + tx * 4 + j;
                float v = acc[r][j];
                if (bias) v += bias[col];
                outp[mg * CDIM + col] = v;
            }
        }
    }
}

// ---------------- 4) flash attention over gathered keys --------------------
// grid: (ceil(N/64), HEADS), block: 256 (16x16), dyn smem: 4 * 64*68 floats
#define SM_STRIDE 68
#define ATTN_SMEM (4 * 64 * SM_STRIDE * (int)sizeof(float))

__global__ __launch_bounds__(256, 2)
void attn_kernel()
{
    extern __shared__ float sm[];
    float* Qs = sm;
    float* Ks = sm + 64 * SM_STRIDE;
    float* Vs = sm + 2 * 64 * SM_STRIDE;
    float* Ps = sm + 3 * 64 * SM_STRIDE;

    const int h  = blockIdx.y;
    const int q0 = blockIdx.x * 64;
    const int M  = g_M;
    const int tid = threadIdx.x;
    const int tx = tid & 15, ty = tid >> 4;

    // load Q tile [64 q][64 d]
    for (int i = tid; i < 64 * 16; i += 256) {
        const int r = i >> 4;
        const int ch = (i & 15) * 4;
        float4 v = make_float4(0.f, 0.f, 0.f, 0.f);
        if (q0 + r < N_Q) v = *(const float4*)&g_q[(q0 + r) * CDIM + h * HDIM + ch];
        *(float4*)&Qs[r * SM_STRIDE + ch] = v;
    }

    float m_run[4] = {-1e30f, -1e30f, -1e30f, -1e30f};
    float l_run[4] = {0.f, 0.f, 0.f, 0.f};
    float accO[4][4] = {};

    const int numTiles = (M + 63) >> 6;
    for (int kt = 0; kt < numTiles; kt++) {
        __syncthreads();   // previous PV done (and Q load on first iter)

        // load K/V tiles [64 k][64 d]
        for (int i = tid; i < 64 * 16; i += 256) {
            const int r = i >> 4;
            const int ch = (i & 15) * 4;
            const int kg = kt * 64 + r;
            float4 kv = make_float4(0.f, 0.f, 0.f, 0.f);
            float4 vv = make_float4(0.f, 0.f, 0.f, 0.f);
            if (kg < M) {
                kv = *(const float4*)&g_k[kg * CDIM + h * HDIM + ch];
                vv = *(const float4*)&g_v[kg * CDIM + h * HDIM + ch];
            }
            *(float4*)&Ks[r * SM_STRIDE + ch] = kv;
            *(float4*)&Vs[r * SM_STRIDE + ch] = vv;
        }
        __syncthreads();

        // S = Q K^T (4x4 microtile per thread)
        float s[4][4] = {};
#pragma unroll
        for (int d4 = 0; d4 < 16; d4++) {
            float4 qv[4], kv[4];
#pragma unroll
            for (int r = 0; r < 4; r++) qv[r] = *(float4*)&Qs[(ty * 4 + r) * SM_STRIDE + d4 * 4];
#pragma unroll
            for (int j = 0; j < 4; j++) kv[j] = *(float4*)&Ks[(tx * 4 + j) * SM_STRIDE + d4 * 4];
#pragma unroll
            for (int r = 0; r < 4; r++)
#pragma unroll
                for (int j = 0; j < 4; j++)
                    s[r][j] += qv[r].x * kv[j].x + qv[r].y * kv[j].y
                             + qv[r].z * kv[j].z + qv[r].w * kv[j].w;
        }

        // online softmax per query row (row group = 16 lanes, width-16 shfl)
#pragma unroll
        for (int r = 0; r < 4; r++) {
#pragma unroll
            for (int j = 0; j < 4; j++) {
                const int kg = kt * 64 + tx * 4 + j;
                s[r][j] = (kg < M) ? s[r][j] * 0.125f : -1e30f;
            }
            float tm = fmaxf(fmaxf(s[r][0], s[r][1]), fmaxf(s[r][2], s[r][3]));
#pragma unroll
            for (int off = 8; off > 0; off >>= 1)
                tm = fmaxf(tm, __shfl_xor_sync(0xffffffffu, tm, off, 16));
            const float mn = fmaxf(m_run[r], tm);
            const float corr = __expf(m_run[r] - mn);
            m_run[r] = mn;
            float p0 = __expf(s[r][0] - mn);
            float p1 = __expf(s[r][1] - mn);
            float p2 = __expf(s[r][2] - mn);
            float p3 = __expf(s[r][3] - mn);
            float rs = p0 + p1 + p2 + p3;
#pragma unroll
            for (int off = 8; off > 0; off >>= 1)
                rs += __shfl_xor_sync(0xffffffffu, rs, off, 16);
            l_run[r] = l_run[r] * corr + rs;
#pragma unroll
            for (int j = 0; j < 4; j++) accO[r][j] *= corr;
            *(float4*)&Ps[(ty * 4 + r) * SM_STRIDE + tx * 4] = make_float4(p0, p1, p2, p3);
        }
        __syncthreads();

        // O += P V
#pragma unroll
        for (int k4 = 0; k4 < 16; k4++) {
            float4 pv[4], vv[4];
#pragma unroll
            for (int r = 0; r < 4; r++) pv[r] = *(float4*)&Ps[(ty * 4 + r) * SM_STRIDE + k4 * 4];
#pragma unroll
            for (int kk = 0; kk < 4; kk++) vv[kk] = *(float4*)&Vs[(k4 * 4 + kk) * SM_STRIDE + tx * 4];
#pragma unroll
            for (int r = 0; r < 4; r++) {
                accO[r][0] += pv[r].x * vv[0].x + pv[r].y * vv[1].x + pv[r].z * vv[2].x + pv[r].w * vv[3].x;
                accO[r][1] += pv[r].x * vv[0].y + pv[r].y * vv[1].y + pv[r].z * vv[2].y + pv[r].w * vv[3].y;
                accO[r][2] += pv[r].x * vv[0].z + pv[r].y * vv[1].z + pv[r].z * vv[2].z + pv[r].w * vv[3].z;
                accO[r][3] += pv[r].x * vv[0].w + pv[r].y * vv[1].w + pv[r].z * vv[2].w + pv[r].w * vv[3].w;
            }
        }
    }

    // normalize + store
#pragma unroll
    for (int r = 0; r < 4; r++) {
        const int qg = q0 + ty * 4 + r;
        if (qg < N_Q) {
            const float inv = 1.0f / l_run[r];
            float4 o = make_float4(accO[r][0] * inv, accO[r][1] * inv,
                                   accO[r][2] * inv, accO[r][3] * inv);
            *(float4*)&g_o[qg * CDIM + h * HDIM + tx * 4] = o;
        }
    }
}

// ---------------- launch ---------------------------------------------------
extern "C" void kernel_launch(void* const* d_in, const int* in_sizes, int n_in,
                              void* d_out, int out_size)
{
    const float* x          = (const float*)d_in[0];
    const float* pos        = (const float*)d_in[1];
    const float* mask       = (const float*)d_in[2];
    const float* mask_block = (const float*)d_in[3];
    const float* Wq         = (const float*)d_in[4];
    const float* Wk         = (const float*)d_in[5];
    const float* Wv         = (const float*)d_in[6];
    const float* Wp         = (const float*)d_in[7];
    const float* bp         = (const float*)d_in[8];
    float* out = (float*)d_out;

    cudaFuncSetAttribute(attn_kernel, cudaFuncAttributeMaxDynamicSharedMemorySize, ATTN_SMEM);

    pool_kernel<<<64, CDIM>>>(x, mask);
    back_finalize_kernel<<<1, CDIM>>>();
    scan_kernel<<<1, 1024>>>(mask, mask_block);

    dim3 gproj((N_KV + 63) / 64, CDIM / 64);   // 65 x 6 covers both N_Q and N_KV/M
    proj_kernel<<<gproj, 256>>>(0, x, pos, Wq, nullptr, nullptr);  // Q
    proj_kernel<<<gproj, 256>>>(1, x, pos, Wk, nullptr, nullptr);  // K (gathered)
    proj_kernel<<<gproj, 256>>>(2, x, pos, Wv, nullptr, nullptr);  // V (gathered)

    dim3 gattn((N_Q + 63) / 64, HEADS);
    attn_kernel<<<gattn, 256, ATTN_SMEM>>>();

    proj_kernel<<<gproj, 256>>>(3, x, pos, Wp, bp, out);           // output proj
}

// round 4
// speedup vs baseline: 2.9797x; 2.9797x over previous
#include <cuda_runtime.h>
#include <cuda_bf16.h>
#include <math.h>

#define N_Q   4098
#define N_KV  4099
#define CDIM  384
#define HEADS 6
#define HDIM  64

// ---------------- scratch (device globals; allocation-free) ----------------
__device__ __align__(16) float g_pp[64 * CDIM];     // pooling partials
__device__ float  g_cntp[64];                       // count partials
__device__ __align__(16) float g_back[CDIM];        // back token
__device__ int    g_idx[N_KV];                      // kept key -> source row
__device__ int    g_M;                              // number of kept keys
__device__ __align__(16) float g_q[N_Q * CDIM];
__device__ __align__(16) float g_k[N_KV * CDIM];
__device__ __align__(16) float g_v[N_KV * CDIM];
__device__ __align__(16) float g_o[N_Q * CDIM];

// ---------------- tf32 helpers --------------------------------------------
__device__ __forceinline__ unsigned f2tf(float x)
{
    unsigned r;
    asm("cvt.rna.tf32.f32 %0, %1;" : "=r"(r) : "f"(x));
    return r;
}

__device__ __forceinline__ void mma8(float* c, const unsigned* a, const unsigned* b)
{
    asm volatile(
        "mma.sync.aligned.m16n8k8.row.col.f32.tf32.tf32.f32 "
        "{%0,%1,%2,%3}, {%4,%5,%6,%7}, {%8,%9}, {%0,%1,%2,%3};\n"
        : "+f"(c[0]), "+f"(c[1]), "+f"(c[2]), "+f"(c[3])
        : "r"(a[0]), "r"(a[1]), "r"(a[2]), "r"(a[3]), "r"(b[0]), "r"(b[1]));
}

// ---------------- 1) background pooling (deterministic, 2-stage) -----------
__global__ void pool_kernel(const float* __restrict__ x, const float* __restrict__ mask)
{
    const int c  = threadIdx.x;            // 384 threads
    const int n0 = blockIdx.x * 64;        // 64 blocks x 64 interior rows = 4096
    float s = 0.f;
    for (int i = 0; i < 64; i++) {
        const int n = n0 + i;
        const float rev = (mask[n] < 0.5f) ? 1.f : 0.f;
        s += rev * x[(1 + n) * CDIM + c];
    }
    g_pp[blockIdx.x * CDIM + c] = s;
    if (c == 0) {
        float cc = 0.f;
        for (int i = 0; i < 64; i++) cc += (mask[n0 + i] < 0.5f) ? 1.f : 0.f;
        g_cntp[blockIdx.x] = cc;
    }
}

__global__ void back_finalize_kernel()
{
    const int c = threadIdx.x;             // 384 threads
    float cnt = 0.f;
    for (int b = 0; b < 64; b++) cnt += g_cntp[b];
    float s = 0.f;
    for (int b = 0; b < 64; b++) s += g_pp[b * CDIM + c];
    g_back[c] = s / (cnt + 1e-10f);
}

// ---------------- 2) kept-key compaction (1-block prefix scan) -------------
__global__ void scan_kernel(const float* __restrict__ mask,
                            const float* __restrict__ mask_block)
{
    __shared__ int sc[1024];
    const int t = threadIdx.x;
    const int base = t * 5;                // 1024*5 >= 4099
    int flags[5];
    int cnt = 0;
#pragma unroll
    for (int e = 0; e < 5; e++) {
        int r = base + e;
        int f = 0;
        if (r < N_KV) {
            float mv = (r >= 1 && r <= N_Q - 2) ? mask[r - 1] : mask_block[r];
            f = (mv >= 0.5f) ? 1 : 0;
        }
        flags[e] = f;
        cnt += f;
    }
    sc[t] = cnt;
    __syncthreads();
    for (int off = 1; off < 1024; off <<= 1) {
        int v = (t >= off) ? sc[t - off] : 0;
        __syncthreads();
        sc[t] += v;
        __syncthreads();
    }
    int o = sc[t] - cnt;                   // exclusive prefix
#pragma unroll
    for (int e = 0; e < 5; e++)
        if (flags[e]) g_idx[o++] = base + e;
    if (t == 1023) g_M = sc[1023];
}

// ---------------- 3) tf32 projection GEMM ----------------------------------
// out[m, j] = sum_c A(m,c) * W[j,c]  (+ bias)
// mode 0: q = (x + pos[:N]) @ Wq^T          -> g_q   (rows = N_Q)
// mode 1: k = (kv_x[idx] + pos[idx]) @ Wk^T -> g_k   (rows = g_M, gathered)
// mode 2: v = kv_x[idx] @ Wv^T              -> g_v   (rows = g_M, gathered)
// mode 3: o = g_o @ Wp^T + bp               -> d_out (rows = N_Q)
// block tile 128(M) x 64(N), k-tile 32, 8 warps in 4(M) x 2(N)
__global__ __launch_bounds__(256)
void proj_tc(int mode,
             const float* __restrict__ x, const float* __restrict__ pos,
             const float* __restrict__ W, const float* __restrict__ bias,
             float* __restrict__ out_param)
{
    __shared__ unsigned As[128][36];
    __shared__ unsigned Ws[64][36];

    const int rows = (mode == 1 || mode == 2) ? g_M : N_Q;
    const int m0 = blockIdx.x * 128;
    if (m0 >= rows) return;
    const int j0 = blockIdx.y * 64;

    float* outp = (mode == 0) ? g_q : (mode == 1) ? g_k : (mode == 2) ? g_v : out_param;

    const int tid  = threadIdx.x;
    const int warp = tid >> 5, lane = tid & 31;
    const int wm = warp >> 1, wn = warp & 1;
    const int g = lane >> 2, t = lane & 3;

    float acc[2][4][4] = {};

    for (int kt = 0; kt < CDIM; kt += 32) {
        // ---- stage A tile 128x32 (mode-specific gather) ----
#pragma unroll
        for (int i = 0; i < 4; i++) {
            const int lin = tid + i * 256;
            const int r = lin >> 3, c4 = (lin & 7) * 4;
            float4 av = make_float4(0.f, 0.f, 0.f, 0.f);
            const int mg = m0 + r;
            if (mg < rows) {
                const int c = kt + c4;
                if (mode == 0) {
                    float4 xv = *(const float4*)&x[mg * CDIM + c];
                    float4 pv = *(const float4*)&pos[mg * CDIM + c];
                    av = make_float4(xv.x + pv.x, xv.y + pv.y, xv.z + pv.z, xv.w + pv.w);
                } else if (mode == 3) {
                    av = *(const float4*)&g_o[mg * CDIM + c];
                } else {
                    const int src = g_idx[mg];
                    float4 bv = (src < N_Q) ? *(const float4*)&x[src * CDIM + c]
                                            : *(const float4*)&g_back[c];
                    if (mode == 1) {
                        float4 pv = *(const float4*)&pos[src * CDIM + c];
                        av = make_float4(bv.x + pv.x, bv.y + pv.y, bv.z + pv.z, bv.w + pv.w);
                    } else {
                        av = bv;
                    }
                }
            }
            As[r][c4 + 0] = f2tf(av.x); As[r][c4 + 1] = f2tf(av.y);
            As[r][c4 + 2] = f2tf(av.z); As[r][c4 + 3] = f2tf(av.w);
        }
        // ---- stage W tile 64x32 ----
#pragma unroll
        for (int i = 0; i < 2; i++) {
            const int lin = tid + i * 256;
            const int r = lin >> 3, c4 = (lin & 7) * 4;
            float4 wv = *(const float4*)&W[(j0 + r) * CDIM + kt + c4];
            Ws[r][c4 + 0] = f2tf(wv.x); Ws[r][c4 + 1] = f2tf(wv.y);
            Ws[r][c4 + 2] = f2tf(wv.z); Ws[r][c4 + 3] = f2tf(wv.w);
        }
        __syncthreads();

#pragma unroll
        for (int ks = 0; ks < 4; ks++) {
            unsigned a[2][4], b[4][2];
#pragma unroll
            for (int mt = 0; mt < 2; mt++) {
                const int rb = wm * 32 + mt * 16;
                a[mt][0] = As[rb + g    ][ks * 8 + t    ];
                a[mt][1] = As[rb + g + 8][ks * 8 + t    ];
                a[mt][2] = As[rb + g    ][ks * 8 + t + 4];
                a[mt][3] = As[rb + g + 8][ks * 8 + t + 4];
            }
#pragma unroll
            for (int nt = 0; nt < 4; nt++) {
                const int jb = wn * 32 + nt * 8;
                b[nt][0] = Ws[jb + g][ks * 8 + t    ];
                b[nt][1] = Ws[jb + g][ks * 8 + t + 4];
            }
#pragma unroll
            for (int mt = 0; mt < 2; mt++)
#pragma unroll
                for (int nt = 0; nt < 4; nt++)
                    mma8(acc[mt][nt], a[mt], b[nt]);
        }
        __syncthreads();
    }

    // epilogue
#pragma unroll
    for (int mt = 0; mt < 2; mt++) {
#pragma unroll
        for (int nt = 0; nt < 4; nt++) {
            const int col = j0 + wn * 32 + nt * 8 + t * 2;
            const float b0 = bias ? bias[col]     : 0.f;
            const float b1 = bias ? bias[col + 1] : 0.f;
            const int r0 = m0 + wm * 32 + mt * 16 + g;
            const int r1 = r0 + 8;
            if (r0 < rows) {
                float2 v = make_float2(acc[mt][nt][0] + b0, acc[mt][nt][1] + b1);
                *(float2*)&outp[r0 * CDIM + col] = v;
            }
            if (r1 < rows) {
                float2 v = make_float2(acc[mt][nt][2] + b0, acc[mt][nt][3] + b1);
                *(float2*)&outp[r1 * CDIM + col] = v;
            }
        }
    }
}

// ---------------- 4) tf32 flash attention ----------------------------------
// grid (ceil(N/64), HEADS), block 128 (4 warps x 16 q-rows each)
#define AT_STRIDE 68
#define ATTN_SMEM (4 * 64 * AT_STRIDE * (int)sizeof(unsigned))

__global__ __launch_bounds__(128)
void attn_tc()
{
    extern __shared__ unsigned sm[];
    unsigned* Qs = sm;                      // [64][68] tf32
    unsigned* Ks = sm + 64 * AT_STRIDE;
    unsigned* Vs = sm + 2 * 64 * AT_STRIDE;
    unsigned* Ps = sm + 3 * 64 * AT_STRIDE; // warp-private 16-row slices

    const int h  = blockIdx.y;
    const int q0 = blockIdx.x * 64;
    const int M  = g_M;
    const int tid = threadIdx.x, warp = tid >> 5, lane = tid & 31;
    const int g = lane >> 2, t = lane & 3;
    const int rb = warp * 16;

    // stage Q tile [64 q][64 d] as tf32
#pragma unroll
    for (int i = 0; i < 8; i++) {
        const int lin = tid + i * 128;
        const int r = lin >> 4, c4 = (lin & 15) * 4;
        float4 v = make_float4(0.f, 0.f, 0.f, 0.f);
        if (q0 + r < N_Q) v = *(const float4*)&g_q[(q0 + r) * CDIM + h * HDIM + c4];
        Qs[r * AT_STRIDE + c4 + 0] = f2tf(v.x); Qs[r * AT_STRIDE + c4 + 1] = f2tf(v.y);
        Qs[r * AT_STRIDE + c4 + 2] = f2tf(v.z); Qs[r * AT_STRIDE + c4 + 3] = f2tf(v.w);
    }

    float m_lo = -1e30f, m_hi = -1e30f, l_lo = 0.f, l_hi = 0.f;
    float co[8][4] = {};

    const int nT = (M + 63) >> 6;
    for (int kt = 0; kt < nT; kt++) {
        __syncthreads();
        // stage K/V tiles [64 k][64 d]
#pragma unroll
        for (int i = 0; i < 8; i++) {
            const int lin = tid + i * 128;
            const int r = lin >> 4, c4 = (lin & 15) * 4;
            const int kg = kt * 64 + r;
            float4 kv = make_float4(0.f, 0.f, 0.f, 0.f);
            float4 vv = make_float4(0.f, 0.f, 0.f, 0.f);
            if (kg < M) {
                kv = *(const float4*)&g_k[kg * CDIM + h * HDIM + c4];
                vv = *(const float4*)&g_v[kg * CDIM + h * HDIM + c4];
            }
            Ks[r * AT_STRIDE + c4 + 0] = f2tf(kv.x); Ks[r * AT_STRIDE + c4 + 1] = f2tf(kv.y);
            Ks[r * AT_STRIDE + c4 + 2] = f2tf(kv.z); Ks[r * AT_STRIDE + c4 + 3] = f2tf(kv.w);
            Vs[r * AT_STRIDE + c4 + 0] = f2tf(vv.x); Vs[r * AT_STRIDE + c4 + 1] = f2tf(vv.y);
            Vs[r * AT_STRIDE + c4 + 2] = f2tf(vv.z); Vs[r * AT_STRIDE + c4 + 3] = f2tf(vv.w);
        }
        __syncthreads();

        // ---- S = Q K^T for this warp's 16 rows x 64 cols ----
        float cs[8][4] = {};
#pragma unroll
        for (int ks = 0; ks < 8; ks++) {
            unsigned a[4];
            a[0] = Qs[(rb + g    ) * AT_STRIDE + ks * 8 + t    ];
            a[1] = Qs[(rb + g + 8) * AT_STRIDE + ks * 8 + t    ];
            a[2] = Qs[(rb + g    ) * AT_STRIDE + ks * 8 + t + 4];
            a[3] = Qs[(rb + g + 8) * AT_STRIDE + ks * 8 + t + 4];
#pragma unroll
            for (int nt = 0; nt < 8; nt++) {
                unsigned b[2];
                b[0] = Ks[(nt * 8 + g) * AT_STRIDE + ks * 8 + t    ];
                b[1] = Ks[(nt * 8 + g) * AT_STRIDE + ks * 8 + t + 4];
                mma8(cs[nt], a, b);
            }
        }

        // ---- online softmax (rows r_lo = rb+g, r_hi = rb+g+8) ----
        float tm_lo = -1e30f, tm_hi = -1e30f;
#pragma unroll
        for (int nt = 0; nt < 8; nt++) {
            const int c0 = kt * 64 + nt * 8 + t * 2;
            cs[nt][0] = (c0     < M) ? cs[nt][0] * 0.125f : -1e30f;
            cs[nt][1] = (c0 + 1 < M) ? cs[nt][1] * 0.125f : -1e30f;
            cs[nt][2] = (c0     < M) ? cs[nt][2] * 0.125f : -1e30f;
            cs[nt][3] = (c0 + 1 < M) ? cs[nt][3] * 0.125f : -1e30f;
            tm_lo = fmaxf(tm_lo, fmaxf(cs[nt][0], cs[nt][1]));
            tm_hi = fmaxf(tm_hi, fmaxf(cs[nt][2], cs[nt][3]));
        }
        tm_lo = fmaxf(tm_lo, __shfl_xor_sync(0xffffffffu, tm_lo, 1));
        tm_lo = fmaxf(tm_lo, __shfl_xor_sync(0xffffffffu, tm_lo, 2));
        tm_hi = fmaxf(tm_hi, __shfl_xor_sync(0xffffffffu, tm_hi, 1));
        tm_hi = fmaxf(tm_hi, __shfl_xor_sync(0xffffffffu, tm_hi, 2));

        const float mn_lo = fmaxf(m_lo, tm_lo);
        const float mn_hi = fmaxf(m_hi, tm_hi);
        const float corr_lo = __expf(m_lo - mn_lo);
        const float corr_hi = __expf(m_hi - mn_hi);
        m_lo = mn_lo; m_hi = mn_hi;

        float rs_lo = 0.f, rs_hi = 0.f;
#pragma unroll
        for (int nt = 0; nt < 8; nt++) {
            const float p0 = __expf(cs[nt][0] - mn_lo);
            const float p1 = __expf(cs[nt][1] - mn_lo);
            const float p2 = __expf(cs[nt][2] - mn_hi);
            const float p3 = __expf(cs[nt][3] - mn_hi);
            rs_lo += p0 + p1;
            rs_hi += p2 + p3;
            const int col = nt * 8 + t * 2;
            uint2 lo = make_uint2(f2tf(p0), f2tf(p1));
            uint2 hi = make_uint2(f2tf(p2), f2tf(p3));
            *(uint2*)&Ps[(rb + g    ) * AT_STRIDE + col] = lo;
            *(uint2*)&Ps[(rb + g + 8) * AT_STRIDE + col] = hi;
        }
        rs_lo += __shfl_xor_sync(0xffffffffu, rs_lo, 1);
        rs_lo += __shfl_xor_sync(0xffffffffu, rs_lo, 2);
        rs_hi += __shfl_xor_sync(0xffffffffu, rs_hi, 1);
        rs_hi += __shfl_xor_sync(0xffffffffu, rs_hi, 2);
        l_lo = l_lo * corr_lo + rs_lo;
        l_hi = l_hi * corr_hi + rs_hi;

#pragma unroll
        for (int nt = 0; nt < 8; nt++) {
            co[nt][0] *= corr_lo; co[nt][1] *= corr_lo;
            co[nt][2] *= corr_hi; co[nt][3] *= corr_hi;
        }
        __syncwarp();    // order Ps stores (cross-lane) before A-frag loads

        // ---- O += P V ----
#pragma unroll
        for (int ks = 0; ks < 8; ks++) {
            unsigned a[4];
            a[0] = Ps[(rb + g    ) * AT_STRIDE + ks * 8 + t    ];
            a[1] = Ps[(rb + g + 8) * AT_STRIDE + ks * 8 + t    ];
            a[2] = Ps[(rb + g    ) * AT_STRIDE + ks * 8 + t + 4];
            a[3] = Ps[(rb + g + 8) * AT_STRIDE + ks * 8 + t + 4];
#pragma unroll
            for (int nt = 0; nt < 8; nt++) {
                unsigned b[2];
                b[0] = Vs[(ks * 8 + t    ) * AT_STRIDE + nt * 8 + g];
                b[1] = Vs[(ks * 8 + t + 4) * AT_STRIDE + nt * 8 + g];
                mma8(co[nt], a, b);
            }
        }
    }

    // ---- normalize + store ----
    const float inv_lo = 1.0f / l_lo;
    const float inv_hi = 1.0f / l_hi;
#pragma unroll
    for (int nt = 0; nt < 8; nt++) {
        const int d  = nt * 8 + t * 2;
        const int r0 = q0 + rb + g;
        const int r1 = r0 + 8;
        if (r0 < N_Q) {
            float2 v = make_float2(co[nt][0] * inv_lo, co[nt][1] * inv_lo);
            *(float2*)&g_o[r0 * CDIM + h * HDIM + d] = v;
        }
        if (r1 < N_Q) {
            float2 v = make_float2(co[nt][2] * inv_hi, co[nt][3] * inv_hi);
            *(float2*)&g_o[r1 * CDIM + h * HDIM + d] = v;
        }
    }
}

// ---------------- launch ---------------------------------------------------
extern "C" void kernel_launch(void* const* d_in, const int* in_sizes, int n_in,
                              void* d_out, int out_size)
{
    const float* x          = (const float*)d_in[0];
    const float* pos        = (const float*)d_in[1];
    const float* mask       = (const float*)d_in[2];
    const float* mask_block = (const float*)d_in[3];
    const float* Wq         = (const float*)d_in[4];
    const float* Wk         = (const float*)d_in[5];
    const float* Wv         = (const float*)d_in[6];
    const float* Wp         = (const float*)d_in[7];
    const float* bp         = (const float*)d_in[8];
    float* out = (float*)d_out;

    cudaFuncSetAttribute(attn_tc, cudaFuncAttributeMaxDynamicSharedMemorySize, ATTN_SMEM);

    pool_kernel<<<64, CDIM>>>(x, mask);
    back_finalize_kernel<<<1, CDIM>>>();
    scan_kernel<<<1, 1024>>>(mask, mask_block);

    dim3 gproj((N_Q + 127) / 128, CDIM / 64);   // 33 x 6
    proj_tc<<<gproj, 256>>>(0, x, pos, Wq, nullptr, nullptr);  // Q
    proj_tc<<<gproj, 256>>>(1, x, pos, Wk, nullptr, nullptr);  // K (gathered)
    proj_tc<<<gproj, 256>>>(2, x, pos, Wv, nullptr, nullptr);  // V (gathered)

    dim3 gattn((N_Q + 63) / 64, HEADS);
    attn_tc<<<gattn, 128, ATTN_SMEM>>>();

    proj_tc<<<gproj, 256>>>(3, x, pos, Wp, bp, out);           // output proj
}

// round 5
// speedup vs baseline: 3.3820x; 1.1350x over previous
#include <cuda_runtime.h>
#include <cuda_bf16.h>
#include <math.h>

#define N_Q   4098
#define N_KV  4099
#define CDIM  384
#define HEADS 6
#define HDIM  64

// ---------------- scratch (device globals; allocation-free) ----------------
__device__ __align__(16) float g_pp[64 * CDIM];     // pooling partials
__device__ float  g_cntp[64];                       // count partials
__device__ __align__(16) float g_back[CDIM];        // back token
__device__ int    g_idx[N_KV];                      // kept key -> source row
__device__ int    g_M;                              // number of kept keys
__device__ __align__(16) float g_q[N_Q * CDIM];
__device__ __align__(16) float g_k[N_KV * CDIM];
__device__ __align__(16) float g_v[N_KV * CDIM];
__device__ __align__(16) float g_o[N_Q * CDIM];

// ---------------- tf32 helpers --------------------------------------------
__device__ __forceinline__ unsigned f2tf(float x)
{
    unsigned r;
    asm("cvt.rna.tf32.f32 %0, %1;" : "=r"(r) : "f"(x));
    return r;
}

__device__ __forceinline__ void mma8(float* c, const unsigned* a, const unsigned* b)
{
    asm volatile(
        "mma.sync.aligned.m16n8k8.row.col.f32.tf32.tf32.f32 "
        "{%0,%1,%2,%3}, {%4,%5,%6,%7}, {%8,%9}, {%0,%1,%2,%3};\n"
        : "+f"(c[0]), "+f"(c[1]), "+f"(c[2]), "+f"(c[3])
        : "r"(a[0]), "r"(a[1]), "r"(a[2]), "r"(a[3]), "r"(b[0]), "r"(b[1]));
}

// ---------------- 1) background pooling (deterministic, 2-stage) -----------
__global__ void pool_kernel(const float* __restrict__ x, const float* __restrict__ mask)
{
    const int c  = threadIdx.x;            // 384 threads
    const int n0 = blockIdx.x * 64;        // 64 blocks x 64 interior rows = 4096
    float s = 0.f;
    for (int i = 0; i < 64; i++) {
        const int n = n0 + i;
        const float rev = (mask[n] < 0.5f) ? 1.f : 0.f;
        s += rev * x[(1 + n) * CDIM + c];
    }
    g_pp[blockIdx.x * CDIM + c] = s;
    if (c == 0) {
        float cc = 0.f;
        for (int i = 0; i < 64; i++) cc += (mask[n0 + i] < 0.5f) ? 1.f : 0.f;
        g_cntp[blockIdx.x] = cc;
    }
}

__global__ void back_finalize_kernel()
{
    const int c = threadIdx.x;             // 384 threads
    float cnt = 0.f;
    for (int b = 0; b < 64; b++) cnt += g_cntp[b];
    float s = 0.f;
    for (int b = 0; b < 64; b++) s += g_pp[b * CDIM + c];
    g_back[c] = s / (cnt + 1e-10f);
}

// ---------------- 2) kept-key compaction (1-block prefix scan) -------------
__global__ void scan_kernel(const float* __restrict__ mask,
                            const float* __restrict__ mask_block)
{
    __shared__ int sc[1024];
    const int t = threadIdx.x;
    const int base = t * 5;                // 1024*5 >= 4099
    int flags[5];
    int cnt = 0;
#pragma unroll
    for (int e = 0; e < 5; e++) {
        int r = base + e;
        int f = 0;
        if (r < N_KV) {
            float mv = (r >= 1 && r <= N_Q - 2) ? mask[r - 1] : mask_block[r];
            f = (mv >= 0.5f) ? 1 : 0;
        }
        flags[e] = f;
        cnt += f;
    }
    sc[t] = cnt;
    __syncthreads();
    for (int off = 1; off < 1024; off <<= 1) {
        int v = (t >= off) ? sc[t - off] : 0;
        __syncthreads();
        sc[t] += v;
        __syncthreads();
    }
    int o = sc[t] - cnt;                   // exclusive prefix
#pragma unroll
    for (int e = 0; e < 5; e++)
        if (flags[e]) g_idx[o++] = base + e;
    if (t == 1023) g_M = sc[1023];
}

// ---------------- 3) tf32 projection GEMM (fused, double-buffered) ---------
// mode = base_mode + blockIdx.z
// mode 0: q = (x + pos[:N]) @ Wq^T          -> g_q   (rows = N_Q)
// mode 1: k = (kv_x[idx] + pos[idx]) @ Wk^T -> g_k   (rows = g_M, gathered)
// mode 2: v = kv_x[idx] @ Wv^T              -> g_v   (rows = g_M, gathered)
// mode 3: o = g_o @ Wp^T + bp               -> d_out (rows = N_Q)
// block tile 128(M) x 64(N), k-tile 32, 8 warps in 4(M) x 2(N)
#define PROJ_SMEM (2 * (128 * 36 + 64 * 36) * (int)sizeof(unsigned))

__global__ __launch_bounds__(256)
void proj_tc(int base_mode,
             const float* __restrict__ x, const float* __restrict__ pos,
             const float* __restrict__ Wq_, const float* __restrict__ Wk_,
             const float* __restrict__ Wv_, const float* __restrict__ Wp_,
             const float* __restrict__ bias,
             float* __restrict__ out_param)
{
    extern __shared__ unsigned smP[];
    unsigned* smA = smP;                      // [2][128][36]
    unsigned* smW = smP + 2 * 128 * 36;       // [2][64][36]
#define AS(b, r, c) smA[(b) * (128 * 36) + (r) * 36 + (c)]
#define WS(b, r, c) smW[(b) * (64 * 36) + (r) * 36 + (c)]

    const int mode = base_mode + blockIdx.z;
    const int rows = (mode == 1 || mode == 2) ? g_M : N_Q;
    const int m0 = blockIdx.x * 128;
    if (m0 >= rows) return;
    const int j0 = blockIdx.y * 64;

    const float* W =
        (mode == 0) ? Wq_ : (mode == 1) ? Wk_ : (mode == 2) ? Wv_ : Wp_;
    float* outp = (mode == 0) ? g_q : (mode == 1) ? g_k : (mode == 2) ? g_v : out_param;

    const int tid  = threadIdx.x;
    const int warp = tid >> 5, lane = tid & 31;
    const int wm = warp >> 1, wn = warp & 1;
    const int g = lane >> 2, t = lane & 3;

    // ---- per-thread source pointers (hoisted out of k-loop) ----
    const float* pA[4];
    const float* pP[4];
    int rA[4];
#pragma unroll
    for (int i = 0; i < 4; i++) {
        const int lin = tid + i * 256;
        rA[i] = lin >> 3;                  // 0..127
        const int mg = m0 + rA[i];
        pA[i] = nullptr; pP[i] = nullptr;
        if (mg < rows) {
            if (mode == 0) {
                pA[i] = x + mg * CDIM;
                pP[i] = pos + mg * CDIM;
            } else if (mode == 3) {
                pA[i] = g_o + mg * CDIM;
            } else {
                const int src = g_idx[mg];
                pA[i] = (src < N_Q) ? (x + src * CDIM) : g_back;
                if (mode == 1) pP[i] = pos + src * CDIM;
            }
        }
    }
    const float* pW[2];
    int rW[2];
#pragma unroll
    for (int i = 0; i < 2; i++) {
        const int lin = tid + i * 256;
        rW[i] = lin >> 3;                  // 0..63
        pW[i] = W + (j0 + rW[i]) * CDIM;
    }
    const int cA = (tid & 7) * 4;          // k-offset within tile for loads

    float4 aReg[4], pReg[4], wReg[2];

#define PREFETCH(kt)                                                          \
    do {                                                                      \
        _Pragma("unroll")                                                     \
        for (int i = 0; i < 4; i++) {                                         \
            aReg[i] = pA[i] ? *(const float4*)(pA[i] + (kt) + cA)             \
                            : make_float4(0.f, 0.f, 0.f, 0.f);                \
            pReg[i] = pP[i] ? *(const float4*)(pP[i] + (kt) + cA)             \
                            : make_float4(0.f, 0.f, 0.f, 0.f);                \
        }                                                                     \
        _Pragma("unroll")                                                     \
        for (int i = 0; i < 2; i++)                                           \
            wReg[i] = *(const float4*)(pW[i] + (kt) + cA);                    \
    } while (0)

#define STORE(buf)                                                            \
    do {                                                                      \
        _Pragma("unroll")                                                     \
        for (int i = 0; i < 4; i++) {                                         \
            AS(buf, rA[i], cA + 0) = f2tf(aReg[i].x + pReg[i].x);             \
            AS(buf, rA[i], cA + 1) = f2tf(aReg[i].y + pReg[i].y);             \
            AS(buf, rA[i], cA + 2) = f2tf(aReg[i].z + pReg[i].z);             \
            AS(buf, rA[i], cA + 3) = f2tf(aReg[i].w + pReg[i].w);             \
        }                                                                     \
        _Pragma("unroll")                                                     \
        for (int i = 0; i < 2; i++) {                                         \
            WS(buf, rW[i], cA + 0) = f2tf(wReg[i].x);                         \
            WS(buf, rW[i], cA + 1) = f2tf(wReg[i].y);                         \
            WS(buf, rW[i], cA + 2) = f2tf(wReg[i].z);                         \
            WS(buf, rW[i], cA + 3) = f2tf(wReg[i].w);                         \
        }                                                                     \
    } while (0)

    float acc[2][4][4] = {};

    PREFETCH(0);
    STORE(0);
    __syncthreads();

    const int NT = CDIM / 32;              // 12
    for (int kt = 0; kt < NT; kt++) {
        const int cur = kt & 1;
        if (kt + 1 < NT) PREFETCH((kt + 1) * 32);

#pragma unroll
        for (int ks = 0; ks < 4; ks++) {
            unsigned a[2][4], b[4][2];
#pragma unroll
            for (int mt = 0; mt < 2; mt++) {
                const int rb = wm * 32 + mt * 16;
                a[mt][0] = AS(cur, rb + g,     ks * 8 + t    );
                a[mt][1] = AS(cur, rb + g + 8, ks * 8 + t    );
                a[mt][2] = AS(cur, rb + g,     ks * 8 + t + 4);
                a[mt][3] = AS(cur, rb + g + 8, ks * 8 + t + 4);
            }
#pragma unroll
            for (int nt = 0; nt < 4; nt++) {
                const int jb = wn * 32 + nt * 8;
                b[nt][0] = WS(cur, jb + g, ks * 8 + t    );
                b[nt][1] = WS(cur, jb + g, ks * 8 + t + 4);
            }
#pragma unroll
            for (int mt = 0; mt < 2; mt++)
#pragma unroll
                for (int nt = 0; nt < 4; nt++)
                    mma8(acc[mt][nt], a[mt], b[nt]);
        }

        if (kt + 1 < NT) STORE(cur ^ 1);
        __syncthreads();
    }

    // epilogue
#pragma unroll
    for (int mt = 0; mt < 2; mt++) {
#pragma unroll
        for (int nt = 0; nt < 4; nt++) {
            const int col = j0 + wn * 32 + nt * 8 + t * 2;
            const float b0 = (mode == 3 && bias) ? bias[col]     : 0.f;
            const float b1 = (mode == 3 && bias) ? bias[col + 1] : 0.f;
            const int r0 = m0 + wm * 32 + mt * 16 + g;
            const int r1 = r0 + 8;
            if (r0 < rows) {
                float2 v = make_float2(acc[mt][nt][0] + b0, acc[mt][nt][1] + b1);
                *(float2*)&outp[r0 * CDIM + col] = v;
            }
            if (r1 < rows) {
                float2 v = make_float2(acc[mt][nt][2] + b0, acc[mt][nt][3] + b1);
                *(float2*)&outp[r1 * CDIM + col] = v;
            }
        }
    }
#undef AS
#undef WS
}

// ---------------- 4) tf32 flash attention (128-query tiles) ----------------
// grid (ceil(N/128), HEADS), block 256 (8 warps x 16 q-rows each)
#define AT_STRIDE 68
#define ATTN_SMEM ((128 + 64 + 64 + 128) * AT_STRIDE * (int)sizeof(unsigned))

__global__ __launch_bounds__(256, 2)
void attn_tc()
{
    extern __shared__ unsigned sm[];
    unsigned* Qs = sm;                            // [128][68] tf32 (pre-scaled)
    unsigned* Ks = sm + 128 * AT_STRIDE;          // [64][68]
    unsigned* Vs = Ks + 64 * AT_STRIDE;           // [64][68]
    unsigned* Ps = Vs + 64 * AT_STRIDE;           // [128][68] warp-private rows

    const int h  = blockIdx.y;
    const int q0 = blockIdx.x * 128;
    const int M  = g_M;
    const int tid = threadIdx.x, warp = tid >> 5, lane = tid & 31;
    const int g = lane >> 2, t = lane & 3;
    const int rb = warp * 16;

    // stage Q tile [128 q][64 d] as tf32, pre-scaled by 1/8 (exact pow2)
#pragma unroll
    for (int i = 0; i < 8; i++) {
        const int lin = tid + i * 256;
        const int r = lin >> 4, c4 = (lin & 15) * 4;
        float4 v = make_float4(0.f, 0.f, 0.f, 0.f);
        if (q0 + r < N_Q) v = *(const float4*)&g_q[(q0 + r) * CDIM + h * HDIM + c4];
        Qs[r * AT_STRIDE + c4 + 0] = f2tf(v.x * 0.125f);
        Qs[r * AT_STRIDE + c4 + 1] = f2tf(v.y * 0.125f);
        Qs[r * AT_STRIDE + c4 + 2] = f2tf(v.z * 0.125f);
        Qs[r * AT_STRIDE + c4 + 3] = f2tf(v.w * 0.125f);
    }

    float m_lo = -1e30f, m_hi = -1e30f, l_lo = 0.f, l_hi = 0.f;
    float co[8][4] = {};

    const int nT = (M + 63) >> 6;
    for (int kt = 0; kt < nT; kt++) {
        __syncthreads();
        // stage K/V tiles [64 k][64 d]
#pragma unroll
        for (int i = 0; i < 4; i++) {
            const int lin = tid + i * 256;
            const int r = lin >> 4, c4 = (lin & 15) * 4;
            const int kg = kt * 64 + r;
            float4 kv = make_float4(0.f, 0.f, 0.f, 0.f);
            float4 vv = make_float4(0.f, 0.f, 0.f, 0.f);
            if (kg < M) {
                kv = *(const float4*)&g_k[kg * CDIM + h * HDIM + c4];
                vv = *(const float4*)&g_v[kg * CDIM + h * HDIM + c4];
            }
            Ks[r * AT_STRIDE + c4 + 0] = f2tf(kv.x); Ks[r * AT_STRIDE + c4 + 1] = f2tf(kv.y);
            Ks[r * AT_STRIDE + c4 + 2] = f2tf(kv.z); Ks[r * AT_STRIDE + c4 + 3] = f2tf(kv.w);
            Vs[r * AT_STRIDE + c4 + 0] = f2tf(vv.x); Vs[r * AT_STRIDE + c4 + 1] = f2tf(vv.y);
            Vs[r * AT_STRIDE + c4 + 2] = f2tf(vv.z); Vs[r * AT_STRIDE + c4 + 3] = f2tf(vv.w);
        }
        __syncthreads();

        // ---- S = Q K^T for this warp's 16 rows x 64 cols ----
        float cs[8][4] = {};
#pragma unroll
        for (int ks = 0; ks < 8; ks++) {
            unsigned a[4];
            a[0] = Qs[(rb + g    ) * AT_STRIDE + ks * 8 + t    ];
            a[1] = Qs[(rb + g + 8) * AT_STRIDE + ks * 8 + t    ];
            a[2] = Qs[(rb + g    ) * AT_STRIDE + ks * 8 + t + 4];
            a[3] = Qs[(rb + g + 8) * AT_STRIDE + ks * 8 + t + 4];
#pragma unroll
            for (int nt = 0; nt < 8; nt++) {
                unsigned b[2];
                b[0] = Ks[(nt * 8 + g) * AT_STRIDE + ks * 8 + t    ];
                b[1] = Ks[(nt * 8 + g) * AT_STRIDE + ks * 8 + t + 4];
                mma8(cs[nt], a, b);
            }
        }

        // ---- online softmax (rows r_lo = rb+g, r_hi = rb+g+8) ----
        float tm_lo = -1e30f, tm_hi = -1e30f;
#pragma unroll
        for (int nt = 0; nt < 8; nt++) {
            const int c0 = kt * 64 + nt * 8 + t * 2;
            if (c0     >= M) { cs[nt][0] = -1e30f; cs[nt][2] = -1e30f; }
            if (c0 + 1 >= M) { cs[nt][1] = -1e30f; cs[nt][3] = -1e30f; }
            tm_lo = fmaxf(tm_lo, fmaxf(cs[nt][0], cs[nt][1]));
            tm_hi = fmaxf(tm_hi, fmaxf(cs[nt][2], cs[nt][3]));
        }
        tm_lo = fmaxf(tm_lo, __shfl_xor_sync(0xffffffffu, tm_lo, 1));
        tm_lo = fmaxf(tm_lo, __shfl_xor_sync(0xffffffffu, tm_lo, 2));
        tm_hi = fmaxf(tm_hi, __shfl_xor_sync(0xffffffffu, tm_hi, 1));
        tm_hi = fmaxf(tm_hi, __shfl_xor_sync(0xffffffffu, tm_hi, 2));

        const float mn_lo = fmaxf(m_lo, tm_lo);
        const float mn_hi = fmaxf(m_hi, tm_hi);
        const float corr_lo = __expf(m_lo - mn_lo);
        const float corr_hi = __expf(m_hi - mn_hi);
        m_lo = mn_lo; m_hi = mn_hi;

        float rs_lo = 0.f, rs_hi = 0.f;
#pragma unroll
        for (int nt = 0; nt < 8; nt++) {
            const float p0 = __expf(cs[nt][0] - mn_lo);
            const float p1 = __expf(cs[nt][1] - mn_lo);
            const float p2 = __expf(cs[nt][2] - mn_hi);
            const float p3 = __expf(cs[nt][3] - mn_hi);
            rs_lo += p0 + p1;
            rs_hi += p2 + p3;
            const int col = nt * 8 + t * 2;
            uint2 lo = make_uint2(f2tf(p0), f2tf(p1));
            uint2 hi = make_uint2(f2tf(p2), f2tf(p3));
            *(uint2*)&Ps[(rb + g    ) * AT_STRIDE + col] = lo;
            *(uint2*)&Ps[(rb + g + 8) * AT_STRIDE + col] = hi;
        }
        rs_lo += __shfl_xor_sync(0xffffffffu, rs_lo, 1);
        rs_lo += __shfl_xor_sync(0xffffffffu, rs_lo, 2);
        rs_hi += __shfl_xor_sync(0xffffffffu, rs_hi, 1);
        rs_hi += __shfl_xor_sync(0xffffffffu, rs_hi, 2);
        l_lo = l_lo * corr_lo + rs_lo;
        l_hi = l_hi * corr_hi + rs_hi;

#pragma unroll
        for (int nt = 0; nt < 8; nt++) {
            co[nt][0] *= corr_lo; co[nt][1] *= corr_lo;
            co[nt][2] *= corr_hi; co[nt][3] *= corr_hi;
        }
        __syncwarp();    // order Ps stores (cross-lane) before A-frag loads

        // ---- O += P V ----
#pragma unroll
        for (int ks = 0; ks < 8; ks++) {
            unsigned a[4];
            a[0] = Ps[(rb + g    ) * AT_STRIDE + ks * 8 + t    ];
            a[1] = Ps[(rb + g + 8) * AT_STRIDE + ks * 8 + t    ];
            a[2] = Ps[(rb + g    ) * AT_STRIDE + ks * 8 + t + 4];
            a[3] = Ps[(rb + g + 8) * AT_STRIDE + ks * 8 + t + 4];
#pragma unroll
            for (int nt = 0; nt < 8; nt++) {
                unsigned b[2];
                b[0] = Vs[(ks * 8 + t    ) * AT_STRIDE + nt * 8 + g];
                b[1] = Vs[(ks * 8 + t + 4) * AT_STRIDE + nt * 8 + g];
                mma8(co[nt], a, b);
            }
        }
    }

    // ---- normalize + store ----
    const float inv_lo = 1.0f / l_lo;
    const float inv_hi = 1.0f / l_hi;
#pragma unroll
    for (int nt = 0; nt < 8; nt++) {
        const int d  = nt * 8 + t * 2;
        const int r0 = q0 + rb + g;
        const int r1 = r0 + 8;
        if (r0 < N_Q) {
            float2 v = make_float2(co[nt][0] * inv_lo, co[nt][1] * inv_lo);
            *(float2*)&g_o[r0 * CDIM + h * HDIM + d] = v;
        }
        if (r1 < N_Q) {
            float2 v = make_float2(co[nt][2] * inv_hi, co[nt][3] * inv_hi);
            *(float2*)&g_o[r1 * CDIM + h * HDIM + d] = v;
        }
    }
}

// ---------------- launch ---------------------------------------------------
extern "C" void kernel_launch(void* const* d_in, const int* in_sizes, int n_in,
                              void* d_out, int out_size)
{
    const float* x          = (const float*)d_in[0];
    const float* pos        = (const float*)d_in[1];
    const float* mask       = (const float*)d_in[2];
    const float* mask_block = (const float*)d_in[3];
    const float* Wq         = (const float*)d_in[4];
    const float* Wk         = (const float*)d_in[5];
    const float* Wv         = (const float*)d_in[6];
    const float* Wp         = (const float*)d_in[7];
    const float* bp         = (const float*)d_in[8];
    float* out = (float*)d_out;

    cudaFuncSetAttribute(attn_tc, cudaFuncAttributeMaxDynamicSharedMemorySize, ATTN_SMEM);
    cudaFuncSetAttribute(proj_tc, cudaFuncAttributeMaxDynamicSharedMemorySize, PROJ_SMEM);

    pool_kernel<<<64, CDIM>>>(x, mask);
    back_finalize_kernel<<<1, CDIM>>>();
    scan_kernel<<<1, 1024>>>(mask, mask_block);

    // fused Q/K/V projection: blockIdx.z = mode 0/1/2
    dim3 gqkv((N_Q + 127) / 128, CDIM / 64, 3);   // 33 x 6 x 3
    proj_tc<<<gqkv, 256, PROJ_SMEM>>>(0, x, pos, Wq, Wk, Wv, Wp, nullptr, nullptr);

    dim3 gattn((N_Q + 127) / 128, HEADS);         // 33 x 6
    attn_tc<<<gattn, 256, ATTN_SMEM>>>();

    // output projection
    dim3 gout((N_Q + 127) / 128, CDIM / 64, 1);
    proj_tc<<<gout, 256, PROJ_SMEM>>>(3, x, pos, Wq, Wk, Wv, Wp, bp, out);
}

// round 6
// speedup vs baseline: 3.7540x; 1.1100x over previous
#include <cuda_runtime.h>
#include <cuda_bf16.h>
#include <math.h>

#define N_Q   4098
#define N_KV  4099
#define CDIM  384
#define HEADS 6
#define HDIM  64

// ---------------- scratch (device globals; allocation-free) ----------------
__device__ __align__(16) float g_pp[64 * CDIM];     // pooling partials
__device__ float  g_cntp[64];                       // count partials
__device__ __align__(16) float g_back[CDIM];        // back token
__device__ int    g_idx[N_KV];                      // kept key -> source row
__device__ int    g_M;                              // number of kept keys
__device__ __align__(16) float g_q[N_Q * CDIM];     // tf32-prerounded, prescaled 1/8
__device__ __align__(16) float g_k[N_KV * CDIM];    // tf32-prerounded
__device__ __align__(16) float g_v[N_KV * CDIM];    // tf32-prerounded
__device__ __align__(16) float g_o[N_Q * CDIM];

// ---------------- helpers ---------------------------------------------------
__device__ __forceinline__ unsigned f2tf(float x)
{
    unsigned r;
    asm("cvt.rna.tf32.f32 %0, %1;" : "=r"(r) : "f"(x));
    return r;
}

__device__ __forceinline__ void mma8(float* c, const unsigned* a, const unsigned* b)
{
    asm volatile(
        "mma.sync.aligned.m16n8k8.row.col.f32.tf32.tf32.f32 "
        "{%0,%1,%2,%3}, {%4,%5,%6,%7}, {%8,%9}, {%0,%1,%2,%3};\n"
        : "+f"(c[0]), "+f"(c[1]), "+f"(c[2]), "+f"(c[3])
        : "r"(a[0]), "r"(a[1]), "r"(a[2]), "r"(a[3]), "r"(b[0]), "r"(b[1]));
}

__device__ __forceinline__ void cp16(unsigned dst, const void* src, int sz)
{
    asm volatile("cp.async.ca.shared.global [%0], [%1], 16, %2;"
                 :: "r"(dst), "l"(src), "r"(sz));
}
#define CP_COMMIT() asm volatile("cp.async.commit_group;")
#define CP_WAIT(n)  asm volatile("cp.async.wait_group %0;" :: "n"(n))

// ---------------- 1) background pooling (deterministic, 2-stage) -----------
__global__ void pool_kernel(const float* __restrict__ x, const float* __restrict__ mask)
{
    const int c  = threadIdx.x;            // 384 threads
    const int n0 = blockIdx.x * 64;        // 64 blocks x 64 interior rows = 4096
    float s = 0.f;
#pragma unroll 8
    for (int i = 0; i < 64; i++) {
        const int n = n0 + i;
        const float rev = (mask[n] < 0.5f) ? 1.f : 0.f;
        s += rev * x[(1 + n) * CDIM + c];
    }
    g_pp[blockIdx.x * CDIM + c] = s;
    if (c == 0) {
        float cc = 0.f;
        for (int i = 0; i < 64; i++) cc += (mask[n0 + i] < 0.5f) ? 1.f : 0.f;
        g_cntp[blockIdx.x] = cc;
    }
}

__global__ void back_finalize_kernel()
{
    const int c = threadIdx.x;             // 384 threads
    float cnt = 0.f;
    for (int b = 0; b < 64; b++) cnt += g_cntp[b];
    float s = 0.f;
    for (int b = 0; b < 64; b++) s += g_pp[b * CDIM + c];
    g_back[c] = s / (cnt + 1e-10f);
}

// ---------------- 2) kept-key compaction (1-block prefix scan) -------------
__global__ void scan_kernel(const float* __restrict__ mask,
                            const float* __restrict__ mask_block)
{
    __shared__ int sc[1024];
    const int t = threadIdx.x;
    const int base = t * 5;                // 1024*5 >= 4099
    int flags[5];
    int cnt = 0;
#pragma unroll
    for (int e = 0; e < 5; e++) {
        int r = base + e;
        int f = 0;
        if (r < N_KV) {
            float mv = (r >= 1 && r <= N_Q - 2) ? mask[r - 1] : mask_block[r];
            f = (mv >= 0.5f) ? 1 : 0;
        }
        flags[e] = f;
        cnt += f;
    }
    sc[t] = cnt;
    __syncthreads();
    for (int off = 1; off < 1024; off <<= 1) {
        int v = (t >= off) ? sc[t - off] : 0;
        __syncthreads();
        sc[t] += v;
        __syncthreads();
    }
    int o = sc[t] - cnt;                   // exclusive prefix
#pragma unroll
    for (int e = 0; e < 5; e++)
        if (flags[e]) g_idx[o++] = base + e;
    if (t == 1023) g_M = sc[1023];
}

// ---------------- 3) tf32 projection GEMM (fused, double-buffered) ---------
// mode = base_mode + blockIdx.z
// mode 0: q = (x + pos[:N]) @ Wq^T * 1/8    -> g_q  (tf32-rounded)
// mode 1: k = (kv_x[idx] + pos[idx]) @ Wk^T -> g_k  (tf32-rounded, gathered)
// mode 2: v = kv_x[idx] @ Wv^T              -> g_v  (tf32-rounded, gathered)
// mode 3: o = g_o @ Wp^T + bp               -> d_out (fp32)
#define PROJ_SMEM (2 * (128 * 36 + 64 * 36) * (int)sizeof(unsigned))

__global__ __launch_bounds__(256)
void proj_tc(int base_mode,
             const float* __restrict__ x, const float* __restrict__ pos,
             const float* __restrict__ Wq_, const float* __restrict__ Wk_,
             const float* __restrict__ Wv_, const float* __restrict__ Wp_,
             const float* __restrict__ bias,
             float* __restrict__ out_param)
{
    extern __shared__ unsigned smP[];
    unsigned* smA = smP;                      // [2][128][36]
    unsigned* smW = smP + 2 * 128 * 36;       // [2][64][36]
#define AS(b, r, c) smA[(b) * (128 * 36) + (r) * 36 + (c)]
#define WS(b, r, c) smW[(b) * (64 * 36) + (r) * 36 + (c)]

    const int mode = base_mode + blockIdx.z;
    const int rows = (mode == 1 || mode == 2) ? g_M : N_Q;
    const int m0 = blockIdx.x * 128;
    if (m0 >= rows) return;
    const int j0 = blockIdx.y * 64;

    const float* W =
        (mode == 0) ? Wq_ : (mode == 1) ? Wk_ : (mode == 2) ? Wv_ : Wp_;
    float* outp = (mode == 0) ? g_q : (mode == 1) ? g_k : (mode == 2) ? g_v : out_param;

    const int tid  = threadIdx.x;
    const int warp = tid >> 5, lane = tid & 31;
    const int wm = warp >> 1, wn = warp & 1;
    const int g = lane >> 2, t = lane & 3;

    // ---- per-thread source pointers (hoisted out of k-loop) ----
    const float* pA[4];
    const float* pP[4];
    int rA[4];
#pragma unroll
    for (int i = 0; i < 4; i++) {
        const int lin = tid + i * 256;
        rA[i] = lin >> 3;                  // 0..127
        const int mg = m0 + rA[i];
        pA[i] = nullptr; pP[i] = nullptr;
        if (mg < rows) {
            if (mode == 0) {
                pA[i] = x + mg * CDIM;
                pP[i] = pos + mg * CDIM;
            } else if (mode == 3) {
                pA[i] = g_o + mg * CDIM;
            } else {
                const int src = g_idx[mg];
                pA[i] = (src < N_Q) ? (x + src * CDIM) : g_back;
                if (mode == 1) pP[i] = pos + src * CDIM;
            }
        }
    }
    const float* pW[2];
    int rW[2];
#pragma unroll
    for (int i = 0; i < 2; i++) {
        const int lin = tid + i * 256;
        rW[i] = lin >> 3;                  // 0..63
        pW[i] = W + (j0 + rW[i]) * CDIM;
    }
    const int cA = (tid & 7) * 4;          // k-offset within tile for loads

    float4 aReg[4], pReg[4], wReg[2];

#define PREFETCH(kt)                                                          \
    do {                                                                      \
        _Pragma("unroll")                                                     \
        for (int i = 0; i < 4; i++) {                                         \
            aReg[i] = pA[i] ? *(const float4*)(pA[i] + (kt) + cA)             \
                            : make_float4(0.f, 0.f, 0.f, 0.f);                \
            pReg[i] = pP[i] ? *(const float4*)(pP[i] + (kt) + cA)             \
                            : make_float4(0.f, 0.f, 0.f, 0.f);                \
        }                                                                     \
        _Pragma("unroll")                                                     \
        for (int i = 0; i < 2; i++)                                           \
            wReg[i] = *(const float4*)(pW[i] + (kt) + cA);                    \
    } while (0)

#define STORE(buf)                                                            \
    do {                                                                      \
        _Pragma("unroll")                                                     \
        for (int i = 0; i < 4; i++) {                                         \
            AS(buf, rA[i], cA + 0) = f2tf(aReg[i].x + pReg[i].x);             \
            AS(buf, rA[i], cA + 1) = f2tf(aReg[i].y + pReg[i].y);             \
            AS(buf, rA[i], cA + 2) = f2tf(aReg[i].z + pReg[i].z);             \
            AS(buf, rA[i], cA + 3) = f2tf(aReg[i].w + pReg[i].w);             \
        }                                                                     \
        _Pragma("unroll")                                                     \
        for (int i = 0; i < 2; i++) {                                         \
            WS(buf, rW[i], cA + 0) = f2tf(wReg[i].x);                         \
            WS(buf, rW[i], cA + 1) = f2tf(wReg[i].y);                         \
            WS(buf, rW[i], cA + 2) = f2tf(wReg[i].z);                         \
            WS(buf, rW[i], cA + 3) = f2tf(wReg[i].w);                         \
        }                                                                     \
    } while (0)

    float acc[2][4][4] = {};

    PREFETCH(0);
    STORE(0);
    __syncthreads();

    const int NT = CDIM / 32;              // 12
    for (int kt = 0; kt < NT; kt++) {
        const int cur = kt & 1;
        if (kt + 1 < NT) PREFETCH((kt + 1) * 32);

#pragma unroll
        for (int ks = 0; ks < 4; ks++) {
            unsigned a[2][4], b[4][2];
#pragma unroll
            for (int mt = 0; mt < 2; mt++) {
                const int rb = wm * 32 + mt * 16;
                a[mt][0] = AS(cur, rb + g,     ks * 8 + t    );
                a[mt][1] = AS(cur, rb + g + 8, ks * 8 + t    );
                a[mt][2] = AS(cur, rb + g,     ks * 8 + t + 4);
                a[mt][3] = AS(cur, rb + g + 8, ks * 8 + t + 4);
            }
#pragma unroll
            for (int nt = 0; nt < 4; nt++) {
                const int jb = wn * 32 + nt * 8;
                b[nt][0] = WS(cur, jb + g, ks * 8 + t    );
                b[nt][1] = WS(cur, jb + g, ks * 8 + t + 4);
            }
#pragma unroll
            for (int mt = 0; mt < 2; mt++)
#pragma unroll
                for (int nt = 0; nt < 4; nt++)
                    mma8(acc[mt][nt], a[mt], b[nt]);
        }

        if (kt + 1 < NT) STORE(cur ^ 1);
        __syncthreads();
    }

    // epilogue: modes 0-2 store tf32-prerounded (mode 0 prescaled by 1/8)
    const float oscale = (mode == 0) ? 0.125f : 1.0f;
#pragma unroll
    for (int mt = 0; mt < 2; mt++) {
#pragma unroll
        for (int nt = 0; nt < 4; nt++) {
            const int col = j0 + wn * 32 + nt * 8 + t * 2;
            const int r0 = m0 + wm * 32 + mt * 16 + g;
            const int r1 = r0 + 8;
            if (mode == 3) {
                const float b0 = bias ? bias[col]     : 0.f;
                const float b1 = bias ? bias[col + 1] : 0.f;
                if (r0 < rows) {
                    float2 v = make_float2(acc[mt][nt][0] + b0, acc[mt][nt][1] + b1);
                    *(float2*)&outp[r0 * CDIM + col] = v;
                }
                if (r1 < rows) {
                    float2 v = make_float2(acc[mt][nt][2] + b0, acc[mt][nt][3] + b1);
                    *(float2*)&outp[r1 * CDIM + col] = v;
                }
            } else {
                if (r0 < rows) {
                    float2 v = make_float2(
                        __uint_as_float(f2tf(acc[mt][nt][0] * oscale)),
                        __uint_as_float(f2tf(acc[mt][nt][1] * oscale)));
                    *(float2*)&outp[r0 * CDIM + col] = v;
                }
                if (r1 < rows) {
                    float2 v = make_float2(
                        __uint_as_float(f2tf(acc[mt][nt][2] * oscale)),
                        __uint_as_float(f2tf(acc[mt][nt][3] * oscale)));
                    *(float2*)&outp[r1 * CDIM + col] = v;
                }
            }
        }
    }
#undef AS
#undef WS
}

// ---------------- 4) tf32 flash attention (cp.async double-buffered) -------
// grid (ceil(N/128), HEADS), block 256 (8 warps x 16 q-rows each)
// smem layout (words): Q[128][68] | K[2][64][68] | V[2][64][72] | P[128][68]
#define AT_STRIDE 68
#define V_STRIDE  72
#define K_OFF (128 * AT_STRIDE)
#define V_OFF (K_OFF + 2 * 64 * AT_STRIDE)
#define P_OFF (V_OFF + 2 * 64 * V_STRIDE)
#define ATTN_SMEM ((P_OFF + 128 * AT_STRIDE) * (int)sizeof(unsigned))

__global__ __launch_bounds__(256)
void attn_tc()
{
    extern __shared__ unsigned sm[];
    unsigned* Qs = sm;
    unsigned* Ps = sm + P_OFF;

    const int h  = blockIdx.y;
    const int q0 = blockIdx.x * 128;
    const int M  = g_M;
    const int tid = threadIdx.x, warp = tid >> 5, lane = tid & 31;
    const int g = lane >> 2, t = lane & 3;
    const int rb = warp * 16;
    const unsigned smB = (unsigned)__cvta_generic_to_shared(sm);

    // ---- async stage Q tile [128 q][64 d] (pre-rounded + pre-scaled) ----
#pragma unroll
    for (int i = 0; i < 8; i++) {
        const int lin = tid + i * 256;
        const int r = lin >> 4, c4 = (lin & 15) * 4;
        cp16(smB + (r * AT_STRIDE + c4) * 4u,
             &g_q[(q0 + r) * CDIM + h * HDIM + c4],
             (q0 + r < N_Q) ? 16 : 0);
    }

#define STAGE_KV(kt, buf)                                                     \
    do {                                                                      \
        _Pragma("unroll")                                                     \
        for (int i = 0; i < 4; i++) {                                         \
            const int lin = tid + i * 256;                                    \
            const int r = lin >> 4, c4 = (lin & 15) * 4;                      \
            const int kg = (kt) * 64 + r;                                     \
            const int sz = (kg < M) ? 16 : 0;                                 \
            cp16(smB + ((K_OFF + (buf) * 64 * AT_STRIDE) + r * AT_STRIDE + c4) * 4u, \
                 &g_k[kg * CDIM + h * HDIM + c4], sz);                        \
            cp16(smB + ((V_OFF + (buf) * 64 * V_STRIDE) + r * V_STRIDE + c4) * 4u,   \
                 &g_v[kg * CDIM + h * HDIM + c4], sz);                        \
        }                                                                     \
    } while (0)

    const int nT = (M + 63) >> 6;
    STAGE_KV(0, 0);
    CP_COMMIT();                           // group: Q + tile0

    float m_lo = -1e30f, m_hi = -1e30f, l_lo = 0.f, l_hi = 0.f;
    float co[8][4] = {};

    for (int kt = 0; kt < nT; kt++) {
        const int cur = kt & 1;
        __syncthreads();                   // all warps done with buffer cur^1
        if (kt + 1 < nT) {
            STAGE_KV(kt + 1, cur ^ 1);
            CP_COMMIT();
            CP_WAIT(1);                    // tile kt's group complete
        } else {
            CP_WAIT(0);
        }
        __syncthreads();                   // tile kt visible to all warps

        const unsigned* Ks = sm + K_OFF + cur * 64 * AT_STRIDE;
        const unsigned* Vs = sm + V_OFF + cur * 64 * V_STRIDE;

        // ---- S = Q K^T for this warp's 16 rows x 64 cols ----
        float cs[8][4] = {};
#pragma unroll
        for (int ks = 0; ks < 8; ks++) {
            unsigned a[4];
            a[0] = Qs[(rb + g    ) * AT_STRIDE + ks * 8 + t    ];
            a[1] = Qs[(rb + g + 8) * AT_STRIDE + ks * 8 + t    ];
            a[2] = Qs[(rb + g    ) * AT_STRIDE + ks * 8 + t + 4];
            a[3] = Qs[(rb + g + 8) * AT_STRIDE + ks * 8 + t + 4];
#pragma unroll
            for (int nt = 0; nt < 8; nt++) {
                unsigned b[2];
                b[0] = Ks[(nt * 8 + g) * AT_STRIDE + ks * 8 + t    ];
                b[1] = Ks[(nt * 8 + g) * AT_STRIDE + ks * 8 + t + 4];
                mma8(cs[nt], a, b);
            }
        }

        // ---- online softmax (rows r_lo = rb+g, r_hi = rb+g+8) ----
        float tm_lo = -1e30f, tm_hi = -1e30f;
#pragma unroll
        for (int nt = 0; nt < 8; nt++) {
            const int c0 = kt * 64 + nt * 8 + t * 2;
            if (c0     >= M) { cs[nt][0] = -1e30f; cs[nt][2] = -1e30f; }
            if (c0 + 1 >= M) { cs[nt][1] = -1e30f; cs[nt][3] = -1e30f; }
            tm_lo = fmaxf(tm_lo, fmaxf(cs[nt][0], cs[nt][1]));
            tm_hi = fmaxf(tm_hi, fmaxf(cs[nt][2], cs[nt][3]));
        }
        tm_lo = fmaxf(tm_lo, __shfl_xor_sync(0xffffffffu, tm_lo, 1));
        tm_lo = fmaxf(tm_lo, __shfl_xor_sync(0xffffffffu, tm_lo, 2));
        tm_hi = fmaxf(tm_hi, __shfl_xor_sync(0xffffffffu, tm_hi, 1));
        tm_hi = fmaxf(tm_hi, __shfl_xor_sync(0xffffffffu, tm_hi, 2));

        const float mn_lo = fmaxf(m_lo, tm_lo);
        const float mn_hi = fmaxf(m_hi, tm_hi);
        const float corr_lo = __expf(m_lo - mn_lo);
        const float corr_hi = __expf(m_hi - mn_hi);
        m_lo = mn_lo; m_hi = mn_hi;

        float rs_lo = 0.f, rs_hi = 0.f;
#pragma unroll
        for (int nt = 0; nt < 8; nt++) {
            const float p0 = __expf(cs[nt][0] - mn_lo);
            const float p1 = __expf(cs[nt][1] - mn_lo);
            const float p2 = __expf(cs[nt][2] - mn_hi);
            const float p3 = __expf(cs[nt][3] - mn_hi);
            rs_lo += p0 + p1;
            rs_hi += p2 + p3;
            const int col = nt * 8 + t * 2;
            uint2 lo = make_uint2(f2tf(p0), f2tf(p1));
            uint2 hi = make_uint2(f2tf(p2), f2tf(p3));
            *(uint2*)&Ps[(rb + g    ) * AT_STRIDE + col] = lo;
            *(uint2*)&Ps[(rb + g + 8) * AT_STRIDE + col] = hi;
        }
        rs_lo += __shfl_xor_sync(0xffffffffu, rs_lo, 1);
        rs_lo += __shfl_xor_sync(0xffffffffu, rs_lo, 2);
        rs_hi += __shfl_xor_sync(0xffffffffu, rs_hi, 1);
        rs_hi += __shfl_xor_sync(0xffffffffu, rs_hi, 2);
        l_lo = l_lo * corr_lo + rs_lo;
        l_hi = l_hi * corr_hi + rs_hi;

#pragma unroll
        for (int nt = 0; nt < 8; nt++) {
            co[nt][0] *= corr_lo; co[nt][1] *= corr_lo;
            co[nt][2] *= corr_hi; co[nt][3] *= corr_hi;
        }
        __syncwarp();    // order Ps stores (cross-lane) before A-frag loads

        // ---- O += P V (V buffer stride 72: conflict-free B loads) ----
#pragma unroll
        for (int ks = 0; ks < 8; ks++) {
            unsigned a[4];
            a[0] = Ps[(rb + g    ) * AT_STRIDE + ks * 8 + t    ];
            a[1] = Ps[(rb + g + 8) * AT_STRIDE + ks * 8 + t    ];
            a[2] = Ps[(rb + g    ) * AT_STRIDE + ks * 8 + t + 4];
            a[3] = Ps[(rb + g + 8) * AT_STRIDE + ks * 8 + t + 4];
#pragma unroll
            for (int nt = 0; nt < 8; nt++) {
                unsigned b[2];
                b[0] = Vs[(ks * 8 + t    ) * V_STRIDE + nt * 8 + g];
                b[1] = Vs[(ks * 8 + t + 4) * V_STRIDE + nt * 8 + g];
                mma8(co[nt], a, b);
            }
        }
    }

    // ---- normalize + store ----
    const float inv_lo = 1.0f / l_lo;
    const float inv_hi = 1.0f / l_hi;
#pragma unroll
    for (int nt = 0; nt < 8; nt++) {
        const int d  = nt * 8 + t * 2;
        const int r0 = q0 + rb + g;
        const int r1 = r0 + 8;
        if (r0 < N_Q) {
            float2 v = make_float2(co[nt][0] * inv_lo, co[nt][1] * inv_lo);
            *(float2*)&g_o[r0 * CDIM + h * HDIM + d] = v;
        }
        if (r1 < N_Q) {
            float2 v = make_float2(co[nt][2] * inv_hi, co[nt][3] * inv_hi);
            *(float2*)&g_o[r1 * CDIM + h * HDIM + d] = v;
        }
    }
#undef STAGE_KV
}

// ---------------- launch ---------------------------------------------------
extern "C" void kernel_launch(void* const* d_in, const int* in_sizes, int n_in,
                              void* d_out, int out_size)
{
    const float* x          = (const float*)d_in[0];
    const float* pos        = (const float*)d_in[1];
    const float* mask       = (const float*)d_in[2];
    const float* mask_block = (const float*)d_in[3];
    const float* Wq         = (const float*)d_in[4];
    const float* Wk         = (const float*)d_in[5];
    const float* Wv         = (const float*)d_in[6];
    const float* Wp         = (const float*)d_in[7];
    const float* bp         = (const float*)d_in[8];
    float* out = (float*)d_out;

    cudaFuncSetAttribute(attn_tc, cudaFuncAttributeMaxDynamicSharedMemorySize, ATTN_SMEM);
    cudaFuncSetAttribute(proj_tc, cudaFuncAttributeMaxDynamicSharedMemorySize, PROJ_SMEM);

    pool_kernel<<<64, CDIM>>>(x, mask);
    back_finalize_kernel<<<1, CDIM>>>();
    scan_kernel<<<1, 1024>>>(mask, mask_block);

    // fused Q/K/V projection: blockIdx.z = mode 0/1/2
    dim3 gqkv((N_Q + 127) / 128, CDIM / 64, 3);   // 33 x 6 x 3
    proj_tc<<<gqkv, 256, PROJ_SMEM>>>(0, x, pos, Wq, Wk, Wv, Wp, nullptr, nullptr);

    dim3 gattn((N_Q + 127) / 128, HEADS);         // 33 x 6
    attn_tc<<<gattn, 256, ATTN_SMEM>>>();

    // output projection
    dim3 gout((N_Q + 127) / 128, CDIM / 64, 1);
    proj_tc<<<gout, 256, PROJ_SMEM>>>(3, x, pos, Wq, Wk, Wv, Wp, bp, out);
}